// round 3
// baseline (speedup 1.0000x reference)
#include <cuda_runtime.h>
#include <math.h>

// Problem dims
#define Bn 512
#define Tn 256
#define Vn 128
#define Hn 512
#define TB (Tn*Bn)      // 131072 rows
#define NOUT 1536       // r(512) | z(512) | h(512) pre-activation columns

// ---------------- device scratch (no allocations allowed) ----------------
__device__ float g_vT[TB*Vn];        // vals   [t][b][v]
__device__ float g_mT[TB*Vn];        // masks  [t][b][v]
__device__ float g_dT[TB*Vn];        // past   [t][b][v]
__device__ float g_xmean[TB*Vn];
__device__ float g_xp[TB*Vn];
__device__ float g_xt[TB*Vn];
__device__ float g_A[(size_t)TB*NOUT];   // bulk pre-activations (xt,mt,bias parts)
__device__ float g_Dh[(size_t)TB*Hn];    // delta_h for all t
__device__ float g_Wcat[NOUT*256];       // [x|m] columns of Wr,Wz,Wh packed
__device__ float g_bcat[NOUT];
__device__ float g_Wrz[1024*512];        // h-columns of Wr (rows 0..511) and Wz (512..1023)
__device__ float g_Whh[512*512];         // h-columns of Wh
__device__ float g_hbuf[Bn*Hn];          // decayed hidden state Dh[t]*h
__device__ float g_rh[Bn*Hn];            // r * h_decayed
__device__ float g_z[Bn*Hn];             // z gate

// grid barrier state (monotonic generation -> replay safe)
__device__ unsigned g_barc;
__device__ volatile unsigned g_barg;

#define NBLK 128

// ---------------- weight packing ----------------
__global__ void pack_weights(const float* __restrict__ Wz, const float* __restrict__ bz,
                             const float* __restrict__ Wr, const float* __restrict__ br,
                             const float* __restrict__ Wh, const float* __restrict__ bh)
{
    int i = blockIdx.x * blockDim.x + threadIdx.x;
    // Wcat: [1536][256]  k<128 -> x cols (0..127), k>=128 -> m cols (640..767) => col = k+512
    if (i < NOUT*256) {
        int n = i >> 8, k = i & 255;
        const float* W = (n < 512) ? Wr : ((n < 1024) ? Wz : Wh);
        int row = (n < 512) ? n : ((n < 1024) ? n - 512 : n - 1024);
        int col = (k < 128) ? k : (k + 512);
        g_Wcat[i] = W[row*768 + col];
        return;
    }
    int j = i - NOUT*256;
    if (j >= 0 && j < 1024*512) {
        int n = j >> 9, k = j & 511;
        g_Wrz[j] = (n < 512) ? Wr[n*768 + 128 + k] : Wz[(n-512)*768 + 128 + k];
        return;
    }
    int l = j - 1024*512;
    if (l >= 0 && l < 512*512) {
        int n = l >> 9, k = l & 511;
        g_Whh[l] = Wh[n*768 + 128 + k];
        return;
    }
    int m = l - 512*512;
    if (m >= 0 && m < NOUT) {
        g_bcat[m] = (m < 512) ? br[m] : ((m < 1024) ? bz[m-512] : bh[m-1024]);
    }
}

// ---------------- P0: transpose + cumulative mean + x_prime recurrence ----------------
__global__ void p0_kernel(const float* __restrict__ vals,
                          const float* __restrict__ masks,
                          const float* __restrict__ past)
{
    int idx = blockIdx.x * blockDim.x + threadIdx.x;  // B*V threads
    if (idx >= Bn*Vn) return;
    int b = idx / Vn, v = idx % Vn;
    const float* vp = vals  + (size_t)b*Tn*Vn + v;
    const float* mp = masks + (size_t)b*Tn*Vn + v;
    const float* dp = past  + (size_t)b*Tn*Vn + v;
    float cmv = 0.f, cm = 0.f, xp = 0.f;
    for (int t = 0; t < Tn; t++) {
        float x = vp[t*Vn], m = mp[t*Vn], d = dp[t*Vn];
        cmv += m * x;
        cm  += m;
        float xmean = (cm > 0.f) ? (cmv / cm) : 0.f;
        xp = m * x + (1.f - m) * xp;
        int o = (t*Bn + b)*Vn + v;
        g_vT[o] = x; g_mT[o] = m; g_dT[o] = d;
        g_xmean[o] = xmean; g_xp[o] = xp;
    }
}

// ---------------- bulk GEMMs: 128x128 tile, 256 threads, 8x8 per thread ----------------
// MODE 0: A = [xt|mT] (K=256), W = g_Wcat, out = g_A (bias added, no activation)
// MODE 1: A = g_dT (K=128),   W = Wgh,    out = g_Dh = exp(-relu(.+bgh))
// MODE 2: A = g_dT (K=128),   W = Wgx,    out = g_xt composite epilogue
template<int MODE>
__global__ void __launch_bounds__(256)
gemm_bulk(const float* __restrict__ Wsrc, const float* __restrict__ bias)
{
    const int KDIM = (MODE == 0) ? 256 : 128;
    __shared__ float As[16][128];
    __shared__ float Bs[16][128];
    const int tid = threadIdx.x;
    const int m0 = blockIdx.x * 128;
    const int n0 = blockIdx.y * 128;
    const int tx = tid & 15, ty = tid >> 4;
    const float* Wp = (MODE == 0) ? g_Wcat : Wsrc;
    const float* bp = (MODE == 0) ? g_bcat : bias;

    float acc[8][8];
#pragma unroll
    for (int i = 0; i < 8; i++)
#pragma unroll
        for (int j = 0; j < 8; j++) acc[i][j] = 0.f;

    for (int kk = 0; kk < KDIM; kk += 16) {
#pragma unroll
        for (int l = 0; l < 2; l++) {
            int idx = (tid + l*256) * 4;
            int lm = idx >> 4, lk = idx & 15;
            float4 va;
            if (MODE == 0) {
                int kg = kk + lk;
                const float* src = (kg < 128) ? (g_xt + (size_t)(m0+lm)*Vn + kg)
                                              : (g_mT + (size_t)(m0+lm)*Vn + (kg-128));
                va = *(const float4*)src;
            } else {
                va = *(const float4*)(g_dT + (size_t)(m0+lm)*Vn + kk + lk);
            }
            As[lk+0][lm] = va.x; As[lk+1][lm] = va.y; As[lk+2][lm] = va.z; As[lk+3][lm] = va.w;
            float4 vb = *(const float4*)(Wp + (size_t)(n0+lm)*KDIM + kk + lk);
            Bs[lk+0][lm] = vb.x; Bs[lk+1][lm] = vb.y; Bs[lk+2][lm] = vb.z; Bs[lk+3][lm] = vb.w;
        }
        __syncthreads();
#pragma unroll
        for (int k2 = 0; k2 < 16; k2++) {
            float a[8], b[8];
            float4 a0 = *(const float4*)&As[k2][ty*8];
            float4 a1 = *(const float4*)&As[k2][ty*8+4];
            float4 b0 = *(const float4*)&Bs[k2][tx*8];
            float4 b1 = *(const float4*)&Bs[k2][tx*8+4];
            a[0]=a0.x; a[1]=a0.y; a[2]=a0.z; a[3]=a0.w; a[4]=a1.x; a[5]=a1.y; a[6]=a1.z; a[7]=a1.w;
            b[0]=b0.x; b[1]=b0.y; b[2]=b0.z; b[3]=b0.w; b[4]=b1.x; b[5]=b1.y; b[6]=b1.z; b[7]=b1.w;
#pragma unroll
            for (int i = 0; i < 8; i++)
#pragma unroll
                for (int j = 0; j < 8; j++) acc[i][j] += a[i] * b[j];
        }
        __syncthreads();
    }

#pragma unroll
    for (int i = 0; i < 8; i++) {
        int m = m0 + ty*8 + i;
#pragma unroll
        for (int j = 0; j < 8; j++) {
            int n = n0 + tx*8 + j;
            float c = acc[i][j] + bp[n];
            if (MODE == 0) {
                g_A[(size_t)m*NOUT + n] = c;
            } else if (MODE == 1) {
                g_Dh[(size_t)m*Hn + n] = expf(-fmaxf(c, 0.f));
            } else {
                float dx = expf(-fmaxf(c, 0.f));
                int o = m*Vn + n;
                float mt = g_mT[o], x = g_vT[o], xp = g_xp[o], xm = g_xmean[o];
                g_xt[o] = mt*x + (1.f - mt)*(dx*xp + (1.f - dx)*xm);
            }
        }
    }
}

// ---------------- persistent sequential kernel ----------------
__device__ __forceinline__ void gsync()
{
    __syncthreads();
    if (threadIdx.x == 0) {
        __threadfence();
        unsigned gen = g_barg;              // read BEFORE arriving
        if (atomicAdd(&g_barc, 1u) == NBLK - 1) {
            g_barc = 0;
            __threadfence();
            g_barg = gen + 1;
        } else {
            while (g_barg == gen) { __nanosleep(64); }
        }
        __threadfence();
    }
    __syncthreads();
}

__global__ void __launch_bounds__(256)
seq_kernel(float* __restrict__ out)
{
    const int tid = threadIdx.x;
    const int bx = blockIdx.x;
    const int tx = tid & 15, ty = tid >> 4;

    // zero hidden state for this replay
    for (int i = bx*256 + tid; i < Bn*Hn; i += NBLK*256) g_hbuf[i] = 0.f;
    gsync();

    __shared__ float As[16][64];
    __shared__ float Bs[16][64];

    const int mt = bx >> 4;           // 0..7  (batch tile, 64 rows)
    const int m0 = mt * 64;
    const int nt = bx & 15;           // 0..15

    for (int t = 0; t < Tn; t++) {
        // ---- phase 1: P[512,1024] = hbuf @ Wrz^T ; r,z gates ----
        {
            const int n0 = nt * 64;
            float acc[4][4] = {{0.f}};
            for (int kk = 0; kk < 512; kk += 16) {
                int idx = tid * 4;
                int lm = idx >> 4, lk = idx & 15;
                float4 va = *(const float4*)(g_hbuf + (m0+lm)*512 + kk + lk);
                As[lk+0][lm] = va.x; As[lk+1][lm] = va.y; As[lk+2][lm] = va.z; As[lk+3][lm] = va.w;
                float4 vb = *(const float4*)(g_Wrz + (size_t)(n0+lm)*512 + kk + lk);
                Bs[lk+0][lm] = vb.x; Bs[lk+1][lm] = vb.y; Bs[lk+2][lm] = vb.z; Bs[lk+3][lm] = vb.w;
                __syncthreads();
#pragma unroll
                for (int k2 = 0; k2 < 16; k2++) {
                    float4 a = *(const float4*)&As[k2][ty*4];
                    float4 b = *(const float4*)&Bs[k2][tx*4];
                    acc[0][0] += a.x*b.x; acc[0][1] += a.x*b.y; acc[0][2] += a.x*b.z; acc[0][3] += a.x*b.w;
                    acc[1][0] += a.y*b.x; acc[1][1] += a.y*b.y; acc[1][2] += a.y*b.z; acc[1][3] += a.y*b.w;
                    acc[2][0] += a.z*b.x; acc[2][1] += a.z*b.y; acc[2][2] += a.z*b.z; acc[2][3] += a.z*b.w;
                    acc[3][0] += a.w*b.x; acc[3][1] += a.w*b.y; acc[3][2] += a.w*b.z; acc[3][3] += a.w*b.w;
                }
                __syncthreads();
            }
            size_t abase = (size_t)t * Bn * NOUT;
#pragma unroll
            for (int i = 0; i < 4; i++) {
                int m = m0 + ty*4 + i;
#pragma unroll
                for (int j = 0; j < 4; j++) {
                    int n = n0 + tx*4 + j;
                    float pre = acc[i][j] + g_A[abase + (size_t)m*NOUT + n];
                    float s = 1.f / (1.f + expf(-pre));
                    if (n < 512) g_rh[m*512 + n] = s * g_hbuf[m*512 + n];
                    else         g_z[m*512 + n - 512] = s;
                }
            }
        }
        gsync();
        // ---- phase 2: Q[512,512] = rh @ Whh^T ; h update + output + decay ----
        {
            const int n0 = nt * 32;
            float acc[4][2] = {{0.f}};
            for (int kk = 0; kk < 512; kk += 16) {
                int idx = tid * 4;
                int lm = idx >> 4, lk = idx & 15;
                float4 va = *(const float4*)(g_rh + (m0+lm)*512 + kk + lk);
                As[lk+0][lm] = va.x; As[lk+1][lm] = va.y; As[lk+2][lm] = va.z; As[lk+3][lm] = va.w;
                if (tid < 128) {
                    int idx2 = tid * 4;
                    int bm = idx2 >> 4, bk = idx2 & 15;
                    float4 vb = *(const float4*)(g_Whh + (size_t)(n0+bm)*512 + kk + bk);
                    Bs[bk+0][bm] = vb.x; Bs[bk+1][bm] = vb.y; Bs[bk+2][bm] = vb.z; Bs[bk+3][bm] = vb.w;
                }
                __syncthreads();
#pragma unroll
                for (int k2 = 0; k2 < 16; k2++) {
                    float4 a = *(const float4*)&As[k2][ty*4];
                    float2 b = *(const float2*)&Bs[k2][tx*2];
                    acc[0][0] += a.x*b.x; acc[0][1] += a.x*b.y;
                    acc[1][0] += a.y*b.x; acc[1][1] += a.y*b.y;
                    acc[2][0] += a.z*b.x; acc[2][1] += a.z*b.y;
                    acc[3][0] += a.w*b.x; acc[3][1] += a.w*b.y;
                }
                __syncthreads();
            }
            size_t abase = (size_t)t * Bn * NOUT;
            size_t obase = (size_t)t * Bn * Hn;
            size_t dbase = (size_t)(t+1) * Bn * Hn;
#pragma unroll
            for (int i = 0; i < 4; i++) {
                int m = m0 + ty*4 + i;
#pragma unroll
                for (int j = 0; j < 2; j++) {
                    int n = n0 + tx*2 + j;
                    float pre = acc[i][j] + g_A[abase + (size_t)m*NOUT + 1024 + n];
                    float ht = tanhf(pre);
                    float hd = g_hbuf[m*512 + n];
                    float z  = g_z[m*512 + n];
                    float hn = (1.f - z)*hd + z*ht;
                    out[obase + (size_t)m*Hn + n] = hn;
                    float dn = (t + 1 < Tn) ? g_Dh[dbase + (size_t)m*Hn + n] : 0.f;
                    g_hbuf[m*512 + n] = dn * hn;   // pre-decayed state for next step
                }
            }
        }
        gsync();
    }
}

// ---------------- launch ----------------
extern "C" void kernel_launch(void* const* d_in, const int* in_sizes, int n_in,
                              void* d_out, int out_size)
{
    const float* vals  = (const float*)d_in[0];
    const float* masks = (const float*)d_in[1];
    const float* past  = (const float*)d_in[2];
    const float* Wz    = (const float*)d_in[3];
    const float* bz    = (const float*)d_in[4];
    const float* Wr    = (const float*)d_in[5];
    const float* br    = (const float*)d_in[6];
    const float* Wh    = (const float*)d_in[7];
    const float* bh    = (const float*)d_in[8];
    const float* Wgx   = (const float*)d_in[9];
    const float* bgx   = (const float*)d_in[10];
    const float* Wgh   = (const float*)d_in[11];
    const float* bgh   = (const float*)d_in[12];
    float* out = (float*)d_out;

    pack_weights<<<4614, 256>>>(Wz, bz, Wr, br, Wh, bh);
    p0_kernel<<<(Bn*Vn)/256, 256>>>(vals, masks, past);
    gemm_bulk<1><<<dim3(TB/128, Hn/128), 256>>>(Wgh, bgh);   // delta_h
    gemm_bulk<2><<<dim3(TB/128, Vn/128), 256>>>(Wgx, bgx);   // delta_x -> xt
    gemm_bulk<0><<<dim3(TB/128, NOUT/128), 256>>>(nullptr, nullptr); // A buffer
    seq_kernel<<<NBLK, 256>>>(out);
}